// round 14
// baseline (speedup 1.0000x reference)
#include <cuda_runtime.h>
#include <cstdint>

#define NHEADS 12
#define HD 64
#define NB 16
#define SEQ 577
#define DIM 768
#define MROWS (NB * SEQ)        // 9232
#define NQKV (3 * DIM)          // 2304
#define NBH (NB * NHEADS)       // 192
#define ATT_SCALE 0.125f
#define EPSF 1e-6f
#define AST 36                  // GEMM smem stride (floats): ldmatrix banks 4r, CF
#define KSTK 68                 // attn K stride: ldmatrix banks 4r, CF
#define PST 68                  // attn P stride: ldmatrix banks 4r, CF
#define VST 72                  // attn V stride: LDS.32 banks 8t+g, CF
#define GBUF (128 * AST * 2)    // floats per gemm stage (9216)
#define KVSTG (64 * KSTK + 64 * VST)   // floats per attn K+V stage (8960)
#define POLPAD 640

// Scratch (no allocations allowed)
__device__ float g_qkv[(size_t)3 * NBH * SEQ * HD];   // [3,B,H,N,64] (tf32-rounded)
__device__ float g_attn[(size_t)MROWS * DIM];         // [B*N, 768]   (tf32-rounded)
__device__ float g_vsum[(size_t)NBH * HD];
__device__ float g_xr[(size_t)MROWS * DIM];           // tf32-rounded x
__device__ float g_wqT[(size_t)NQKV * DIM];           // rounded Wqkv^T [n][k]
__device__ float g_wpT[(size_t)DIM * DIM];            // rounded Wproj^T [n][k]

__device__ __forceinline__ uint32_t f2tf32(float x) {
    uint32_t r;
    asm("cvt.rna.tf32.f32 %0, %1;" : "=r"(r) : "f"(x));
    return r;
}
__device__ __forceinline__ void mma1688(float d[4], const uint32_t a[4], const uint32_t b[2]) {
    asm volatile(
        "mma.sync.aligned.m16n8k8.row.col.f32.tf32.tf32.f32 "
        "{%0,%1,%2,%3}, {%4,%5,%6,%7}, {%8,%9}, {%0,%1,%2,%3};"
        : "+f"(d[0]), "+f"(d[1]), "+f"(d[2]), "+f"(d[3])
        : "r"(a[0]), "r"(a[1]), "r"(a[2]), "r"(a[3]), "r"(b[0]), "r"(b[1]));
}
__device__ __forceinline__ void ldsm4(uint32_t& r0, uint32_t& r1, uint32_t& r2,
                                      uint32_t& r3, uint32_t addr) {
    asm volatile("ldmatrix.sync.aligned.m8n8.x4.shared.b16 {%0,%1,%2,%3}, [%4];"
                 : "=r"(r0), "=r"(r1), "=r"(r2), "=r"(r3) : "r"(addr));
}
__device__ __forceinline__ float4 round4(float4 v) {
    float4 w;
    w.x = __uint_as_float(f2tf32(v.x));
    w.y = __uint_as_float(f2tf32(v.y));
    w.z = __uint_as_float(f2tf32(v.z));
    w.w = __uint_as_float(f2tf32(v.w));
    return w;
}
__device__ __forceinline__ uint32_t smem_u32(const void* p) {
    uint32_t a;
    asm("{ .reg .u64 t; cvta.to.shared.u64 t, %1; cvt.u32.u64 %0, t; }" : "=r"(a) : "l"(p));
    return a;
}
__device__ __forceinline__ void cpasync16(uint32_t dst, const void* src, int szbytes) {
    asm volatile("cp.async.ca.shared.global [%0], [%1], 16, %2;"
                 :: "r"(dst), "l"(src), "r"(szbytes));
}

// ---------------------------------------------------------------------------
__global__ __launch_bounds__(256) void round_buf(const float4* __restrict__ in,
                                                 float4* __restrict__ out, int n4) {
    int i = blockIdx.x * blockDim.x + threadIdx.x;
    int stride = gridDim.x * blockDim.x;
    for (; i < n4; i += stride) out[i] = round4(in[i]);
}

__global__ __launch_bounds__(256) void round_tr(const float* __restrict__ W,
                                                float* __restrict__ Wt,
                                                int Kdim, int Ncols) {
    __shared__ float tb[32][33];
    const int n0 = blockIdx.x * 32, k0 = blockIdx.y * 32;
#pragma unroll
    for (int i = threadIdx.y; i < 32; i += 8)
        tb[i][threadIdx.x] = W[(size_t)(k0 + i) * Ncols + n0 + threadIdx.x];
    __syncthreads();
#pragma unroll
    for (int i = threadIdx.y; i < 32; i += 8)
        Wt[(size_t)(n0 + i) * Kdim + k0 + threadIdx.x] =
            __uint_as_float(f2tf32(tb[threadIdx.x][i]));
}

// ---------------------------------------------------------------------------
// tf32 mma GEMM (R13-validated, unchanged).
// ---------------------------------------------------------------------------
__global__ __launch_bounds__(256, 2) void gemm_mma(const float* __restrict__ A,
                                                   const float* __restrict__ Bt,
                                                   const float* __restrict__ bias,
                                                   float* __restrict__ outp,
                                                   int Mtotal, int mode) {
    extern __shared__ float smg[];
    const uint32_t sbase = smem_u32(smg);

    const int tid = threadIdx.x;
    const int lane = tid & 31, wid = tid >> 5;
    const int warpM = wid >> 1, warpN = wid & 1;
    const int g = lane >> 2, t = lane & 3;
    const int m0 = blockIdx.y * 128, n0 = blockIdx.x * 128;

    uint32_t aoff[2];
#pragma unroll
    for (int mf = 0; mf < 2; mf++)
        aoff[mf] = ((warpM * 32 + mf * 16 + (lane & 15)) * AST + ((lane >> 4) & 1) * 4) * 4;
    uint32_t boff[4];
#pragma unroll
    for (int p = 0; p < 4; p++)
        boff[p] = (128 * AST +
                   (warpN * 64 + p * 16 + (lane >> 4) * 8 + (lane & 7)) * AST +
                   ((lane >> 3) & 1) * 4) * 4;

#define STAGE(kt, b)                                                              \
    {                                                                             \
        const int k0 = (kt) * 32;                                                 \
        const uint32_t base = sbase + (uint32_t)(b) * (GBUF * 4);                 \
        _Pragma("unroll")                                                         \
        for (int u = 0; u < 4; u++) {                                             \
            int idx = tid + u * 256;                                              \
            int r = idx >> 3, c4 = idx & 7;                                       \
            int row = m0 + r;                                                     \
            int rc = row < Mtotal ? row : Mtotal - 1;                             \
            cpasync16(base + (uint32_t)(r * AST + c4 * 4) * 4,                    \
                      A + (size_t)rc * DIM + k0 + c4 * 4,                         \
                      row < Mtotal ? 16 : 0);                                     \
        }                                                                         \
        _Pragma("unroll")                                                         \
        for (int u = 0; u < 4; u++) {                                             \
            int idx = tid + u * 256;                                              \
            int r = idx >> 3, c4 = idx & 7;                                       \
            cpasync16(base + (uint32_t)(128 * AST + r * AST + c4 * 4) * 4,        \
                      Bt + (size_t)(n0 + r) * DIM + k0 + c4 * 4, 16);             \
        }                                                                         \
    }

    float d[2][8][4];
#pragma unroll
    for (int i = 0; i < 2; i++)
#pragma unroll
        for (int j = 0; j < 8; j++)
#pragma unroll
            for (int c = 0; c < 4; c++) d[i][j][c] = 0.f;

    STAGE(0, 0);
    asm volatile("cp.async.commit_group;");
    asm volatile("cp.async.wait_group 0;");
    __syncthreads();

    for (int kt = 0; kt < 24; kt++) {
        const int cur = kt & 1;
        if (kt < 23) {
            STAGE(kt + 1, 1 - cur);
            asm volatile("cp.async.commit_group;");
        }

        const uint32_t bufb = sbase + (uint32_t)cur * (GBUF * 4);
#pragma unroll
        for (int ks = 0; ks < 4; ks++) {
            const uint32_t kboff = ks * 8 * 4;
            uint32_t af[2][4], bf[8][2];
#pragma unroll
            for (int mf = 0; mf < 2; mf++)
                ldsm4(af[mf][0], af[mf][1], af[mf][2], af[mf][3],
                      bufb + aoff[mf] + kboff);
#pragma unroll
            for (int p = 0; p < 4; p++)
                ldsm4(bf[2 * p][0], bf[2 * p][1], bf[2 * p + 1][0], bf[2 * p + 1][1],
                      bufb + boff[p] + kboff);
#pragma unroll
            for (int mf = 0; mf < 2; mf++)
#pragma unroll
                for (int nf = 0; nf < 8; nf++) mma1688(d[mf][nf], af[mf], bf[nf]);
        }
        if (kt < 23) asm volatile("cp.async.wait_group 0;");
        __syncthreads();
    }

#pragma unroll
    for (int mf = 0; mf < 2; mf++) {
#pragma unroll
        for (int half = 0; half < 2; half++) {
            int row = m0 + warpM * 32 + mf * 16 + g + half * 8;
            if (row >= Mtotal) continue;
            int b_ = row / SEQ, n = row - (row / SEQ) * SEQ;
#pragma unroll
            for (int nf = 0; nf < 8; nf++) {
                int col = n0 + warpN * 64 + nf * 8 + 2 * t;
                float2 w;
                w.x = d[mf][nf][half * 2 + 0] + bias[col + 0];
                w.y = d[mf][nf][half * 2 + 1] + bias[col + 1];
                if (mode == 0) {
                    w.x = __uint_as_float(f2tf32(w.x));
                    w.y = __uint_as_float(f2tf32(w.y));
                    int s = col / DIM;
                    int rem = col - s * DIM;
                    int h = rem >> 6, dd = rem & 63;
                    *(float2*)(g_qkv +
                        (((size_t)s * NBH + b_ * NHEADS + h) * SEQ + n) * HD + dd) = w;
                } else {
                    *(float2*)(outp + (size_t)row * DIM + col) = w;
                }
            }
        }
    }
#undef STAGE
}

// ---------------------------------------------------------------------------
__global__ __launch_bounds__(256) void vsum_kernel() {
    __shared__ float part[4][64];
    const int bh = blockIdx.x;
    const int c = threadIdx.x & 63, gr = threadIdx.x >> 6;
    const float* Vg = g_qkv + (size_t)(2 * NBH + bh) * SEQ * HD;
    float s = 0.f;
    for (int k = gr; k < SEQ; k += 4) s += Vg[(size_t)k * HD + c];
    part[gr][c] = s;
    __syncthreads();
    if (gr == 0)
        g_vsum[bh * HD + c] = part[0][c] + part[1][c] + part[2][c] + part[3][c];
}

// ---------------------------------------------------------------------------
// Tensor-core attention: DOUBLE-BUFFERED cp.async K/V pipeline (R8 pattern),
// ldmatrix K/P frags, LDS.32 V frags, policy staged once.
// smem: 2 x (K 64xKSTK + V 64xVST) + P 128xPST + POLPAD = 106.5 KB
// ---------------------------------------------------------------------------
__global__ __launch_bounds__(256, 2) void attn_mma(const float* __restrict__ policy) {
    extern __shared__ float sm[];
    const uint32_t sbase = smem_u32(sm);
    float* Ps = sm + 2 * KVSTG;
    float* polAll = sm + 2 * KVSTG + 128 * PST;
    const uint32_t psBase = sbase + (uint32_t)(2 * KVSTG) * 4;

    const int bh = blockIdx.y;
    const int b_ = bh / NHEADS, h = bh % NHEADS;
    const int q0 = blockIdx.x * 128;
    const float* Qg = g_qkv + (size_t)bh * SEQ * HD;
    const float* Kg = g_qkv + (size_t)(NBH + bh) * SEQ * HD;
    const float* Vg = g_qkv + (size_t)(2 * NBH + bh) * SEQ * HD;

    const int tid = threadIdx.x;
    const int lane = tid & 31, w = tid >> 5;
    const int g = lane >> 2, t = lane & 3;
    const int r0 = q0 + w * 16 + g;

    for (int i = tid; i < POLPAD; i += 256)
        polAll[i] = (i < SEQ) ? policy[b_ * SEQ + i] : 0.f;

    // hoisted ldmatrix lane offsets (relative to stage base)
    uint32_t koff[4];
#pragma unroll
    for (int p = 0; p < 4; p++)
        koff[p] = ((p * 16 + (lane >> 4) * 8 + (lane & 7)) * KSTK +
                   ((lane >> 3) & 1) * 4) * 4;
    const uint32_t poff = ((w * 16 + (lane & 15)) * PST + ((lane >> 4) & 1) * 4) * 4;

    // stage chunk kc's K+V into buffer b
#define STAGE_KV(kc, b)                                                           \
    {                                                                             \
        const int kb = (kc) * 64;                                                 \
        const uint32_t base = sbase + (uint32_t)(b) * (KVSTG * 4);                \
        _Pragma("unroll")                                                         \
        for (int u = 0; u < 4; u++) {                                             \
            int idx = tid + u * 256;                                              \
            int r = idx >> 4, c4 = idx & 15;                                      \
            int row = kb + r;                                                     \
            int rc = row < SEQ ? row : SEQ - 1;                                   \
            cpasync16(base + (uint32_t)(r * KSTK + c4 * 4) * 4,                   \
                      Kg + (size_t)rc * HD + c4 * 4, row < SEQ ? 16 : 0);         \
        }                                                                         \
        _Pragma("unroll")                                                         \
        for (int u = 0; u < 4; u++) {                                             \
            int idx = tid + u * 256;                                              \
            int r = idx >> 4, c4 = idx & 15;                                      \
            int row = kb + r;                                                     \
            int rc = row < SEQ ? row : SEQ - 1;                                   \
            cpasync16(base + (uint32_t)(64 * KSTK * 4 + (r * VST + c4 * 4) * 4),  \
                      Vg + (size_t)rc * HD + c4 * 4, row < SEQ ? 16 : 0);         \
        }                                                                         \
    }

    // Q frags in registers (canonical slot order)
    uint32_t aq[8][4];
#pragma unroll
    for (int ks = 0; ks < 8; ks++) {
        int c = ks * 8 + t;
        aq[ks][0] = (r0 < SEQ)     ? f2tf32(Qg[(size_t)r0 * HD + c])           : 0u;
        aq[ks][1] = (r0 + 8 < SEQ) ? f2tf32(Qg[(size_t)(r0 + 8) * HD + c])     : 0u;
        aq[ks][2] = (r0 < SEQ)     ? f2tf32(Qg[(size_t)r0 * HD + c + 4])       : 0u;
        aq[ks][3] = (r0 + 8 < SEQ) ? f2tf32(Qg[(size_t)(r0 + 8) * HD + c + 4]) : 0u;
    }

    float mrow[2] = {-1e30f, -1e30f}, lrow[2] = {0.f, 0.f};
    float o[8][4];
#pragma unroll
    for (int nf = 0; nf < 8; nf++)
#pragma unroll
        for (int c = 0; c < 4; c++) o[nf][c] = 0.f;

    STAGE_KV(0, 0);
    asm volatile("cp.async.commit_group;");
    asm volatile("cp.async.wait_group 0;");
    __syncthreads();

    for (int kc = 0; kc < 10; kc++) {
        const int kb = kc * 64;
        const int cur = kc & 1;
        if (kc < 9) {
            STAGE_KV(kc + 1, 1 - cur);
            asm volatile("cp.async.commit_group;");
        }

        const uint32_t ksBase = sbase + (uint32_t)cur * (KVSTG * 4);
        const float* Vs = sm + cur * KVSTG + 64 * KSTK;

        // S = Q K^T (K frags via ldmatrix)
        float s[8][4];
#pragma unroll
        for (int nf = 0; nf < 8; nf++)
#pragma unroll
            for (int c = 0; c < 4; c++) s[nf][c] = 0.f;
#pragma unroll
        for (int ks = 0; ks < 8; ks++) {
            const uint32_t kcoff = ks * 8 * 4;
            uint32_t bf[8][2];
#pragma unroll
            for (int p = 0; p < 4; p++)
                ldsm4(bf[2 * p][0], bf[2 * p][1], bf[2 * p + 1][0], bf[2 * p + 1][1],
                      ksBase + koff[p] + kcoff);
#pragma unroll
            for (int nf = 0; nf < 8; nf++) mma1688(s[nf], aq[ks], bf[nf]);
        }

#pragma unroll
        for (int nf = 0; nf < 8; nf++)
#pragma unroll
            for (int c = 0; c < 4; c++) {
                int key = kb + nf * 8 + 2 * t + (c & 1);
                s[nf][c] = (key < SEQ) ? s[nf][c] * ATT_SCALE : -1e30f;
            }

#pragma unroll
        for (int half = 0; half < 2; half++) {
            const int qglob = r0 + 8 * half;
            float rm = -1e30f;
#pragma unroll
            for (int nf = 0; nf < 8; nf++)
                rm = fmaxf(rm, fmaxf(s[nf][half * 2], s[nf][half * 2 + 1]));
            rm = fmaxf(rm, __shfl_xor_sync(0xffffffffu, rm, 1));
            rm = fmaxf(rm, __shfl_xor_sync(0xffffffffu, rm, 2));
            float nm = fmaxf(mrow[half], rm);
            float corr = __expf(mrow[half] - nm);
            mrow[half] = nm;
            float ls = 0.f;
#pragma unroll
            for (int nf = 0; nf < 8; nf++) {
#pragma unroll
                for (int c = 0; c < 2; c++) {
                    int kl = nf * 8 + 2 * t + c;
                    int key = kb + kl;
                    bool keep = (polAll[kb + kl] > 0.5f) || (key == qglob);
                    float p = keep ? __expf(s[nf][half * 2 + c] - nm) : 0.f;
                    s[nf][half * 2 + c] = p;
                    ls += p;
                }
            }
            ls += __shfl_xor_sync(0xffffffffu, ls, 1);
            ls += __shfl_xor_sync(0xffffffffu, ls, 2);
            lrow[half] = lrow[half] * corr + ls;
#pragma unroll
            for (int nf = 0; nf < 8; nf++) {
                o[nf][half * 2] *= corr;
                o[nf][half * 2 + 1] *= corr;
            }
        }

        // P -> smem (warp-private rows; no barrier needed)
#pragma unroll
        for (int nf = 0; nf < 8; nf++) {
#pragma unroll
            for (int half = 0; half < 2; half++) {
                float2 pv;
                pv.x = __uint_as_float(f2tf32(s[nf][half * 2]));
                pv.y = __uint_as_float(f2tf32(s[nf][half * 2 + 1]));
                *(float2*)(Ps + (w * 16 + g + 8 * half) * PST + nf * 8 + 2 * t) = pv;
            }
        }

        // O += P V  (P frag via ldmatrix; V canonical rows kcol+t, kcol+t+4)
#pragma unroll
        for (int ks = 0; ks < 8; ks++) {
            const int kcol = ks * 8;
            uint32_t ap[4];
            ldsm4(ap[0], ap[1], ap[2], ap[3], psBase + poff + (uint32_t)kcol * 4);
#pragma unroll
            for (int nf = 0; nf < 8; nf++) {
                int c0 = nf * 8 + g;
                uint32_t bf[2];
                bf[0] = __float_as_uint(Vs[(kcol + t) * VST + c0]);
                bf[1] = __float_as_uint(Vs[(kcol + t + 4) * VST + c0]);
                mma1688(o[nf], ap, bf);
            }
        }

        if (kc < 9) {
            asm volatile("cp.async.wait_group 0;");
            __syncthreads();
        }
    }
#undef STAGE_KV

    const float epsn = EPSF / (float)SEQ;
#pragma unroll
    for (int half = 0; half < 2; half++) {
        int qglob = r0 + 8 * half;
        if (qglob >= SEQ) continue;
        float inv = 1.f / (lrow[half] + EPSF);
#pragma unroll
        for (int nf = 0; nf < 8; nf++) {
            int dd = nf * 8 + 2 * t;
            float2 vs = *(const float2*)(g_vsum + bh * HD + dd);
            float2 ww;
            ww.x = __uint_as_float(f2tf32((o[nf][half * 2] + epsn * vs.x) * inv));
            ww.y = __uint_as_float(f2tf32((o[nf][half * 2 + 1] + epsn * vs.y) * inv));
            *(float2*)(g_attn + ((size_t)b_ * SEQ + qglob) * DIM + h * HD + dd) = ww;
        }
    }
}

// ---------------------------------------------------------------------------
extern "C" void kernel_launch(void* const* d_in, const int* in_sizes, int n_in,
                              void* d_out, int out_size) {
    const float* x      = (const float*)d_in[0];
    const float* policy = (const float*)d_in[1];
    const float* Wqkv   = (const float*)d_in[2];
    const float* bqkv   = (const float*)d_in[3];
    const float* Wproj  = (const float*)d_in[4];
    const float* bproj  = (const float*)d_in[5];
    float* out = (float*)d_out;
    (void)in_sizes; (void)n_in; (void)out_size;

    void *p_attn = nullptr, *p_xr = nullptr, *p_wqT = nullptr, *p_wpT = nullptr;
    cudaGetSymbolAddress(&p_attn, g_attn);
    cudaGetSymbolAddress(&p_xr, g_xr);
    cudaGetSymbolAddress(&p_wqT, g_wqT);
    cudaGetSymbolAddress(&p_wpT, g_wpT);

    // 0) pre-round x; round+transpose weights to [n][k]
    round_buf<<<1184, 256>>>((const float4*)x, (float4*)p_xr, MROWS * DIM / 4);
    dim3 tb(32, 8);
    round_tr<<<dim3(NQKV / 32, DIM / 32), tb>>>(Wqkv, (float*)p_wqT, DIM, NQKV);
    round_tr<<<dim3(DIM / 32, DIM / 32), tb>>>(Wproj, (float*)p_wpT, DIM, DIM);

    const int gsmem = 2 * GBUF * 4;   // 73728 B
    cudaFuncSetAttribute(gemm_mma, cudaFuncAttributeMaxDynamicSharedMemorySize, gsmem);

    // 1) QKV projection, scatter (rounded) to [3,B,H,N,64]
    dim3 g1(NQKV / 128, (MROWS + 127) / 128);
    gemm_mma<<<g1, 256, gsmem>>>((const float*)p_xr, (const float*)p_wqT, bqkv,
                                 nullptr, MROWS, 0);

    // 1b) per-(b,h) V column sums
    vsum_kernel<<<NBH, 256>>>();

    // 2) tensor-core policy-masked flash attention (double-buffered K/V)
    const int asmem = (2 * KVSTG + 128 * PST + POLPAD) * 4;  // 109056 B
    cudaFuncSetAttribute(attn_mma, cudaFuncAttributeMaxDynamicSharedMemorySize, asmem);
    dim3 g2((SEQ + 127) / 128, NBH);
    attn_mma<<<g2, 256, asmem>>>(policy);

    // 3) output projection
    dim3 g3(DIM / 128, (MROWS + 127) / 128);
    gemm_mma<<<g3, 256, gsmem>>>((const float*)p_attn, (const float*)p_wpT, bproj,
                                 out, MROWS, 1);
}

// round 15
// speedup vs baseline: 1.0211x; 1.0211x over previous
#include <cuda_runtime.h>
#include <cstdint>

#define NHEADS 12
#define HD 64
#define NB 16
#define SEQ 577
#define DIM 768
#define MROWS (NB * SEQ)        // 9232
#define NQKV (3 * DIM)          // 2304
#define NBH (NB * NHEADS)       // 192
#define ATT_SCALE 0.125f
#define EPSF 1e-6f
#define AST 36                  // GEMM smem stride (floats): ldmatrix banks 4r, CF
#define KSTK 68                 // attn K stride: ldmatrix banks 4r, CF
#define PST 68                  // attn P stride: ldmatrix banks 4r, CF
#define VST 72                  // attn V stride: LDS.32 banks 8t+g, CF
#define GBUF (128 * AST * 2)    // floats per gemm stage (9216)
#define POLPAD 640

// Scratch (no allocations allowed)
__device__ float g_qkv[(size_t)3 * NBH * SEQ * HD];   // [3,B,H,N,64] (tf32-rounded)
__device__ float g_attn[(size_t)MROWS * DIM];         // [B*N, 768]   (tf32-rounded)
__device__ float g_vsum[(size_t)NBH * HD];
__device__ float g_xr[(size_t)MROWS * DIM];           // tf32-rounded x
__device__ float g_wqT[(size_t)NQKV * DIM];           // rounded Wqkv^T [n][k]
__device__ float g_wpT[(size_t)DIM * DIM];            // rounded Wproj^T [n][k]

__device__ __forceinline__ uint32_t f2tf32(float x) {
    uint32_t r;
    asm("cvt.rna.tf32.f32 %0, %1;" : "=r"(r) : "f"(x));
    return r;
}
__device__ __forceinline__ void mma1688(float d[4], const uint32_t a[4], const uint32_t b[2]) {
    asm volatile(
        "mma.sync.aligned.m16n8k8.row.col.f32.tf32.tf32.f32 "
        "{%0,%1,%2,%3}, {%4,%5,%6,%7}, {%8,%9}, {%0,%1,%2,%3};"
        : "+f"(d[0]), "+f"(d[1]), "+f"(d[2]), "+f"(d[3])
        : "r"(a[0]), "r"(a[1]), "r"(a[2]), "r"(a[3]), "r"(b[0]), "r"(b[1]));
}
__device__ __forceinline__ void ldsm4(uint32_t& r0, uint32_t& r1, uint32_t& r2,
                                      uint32_t& r3, uint32_t addr) {
    asm volatile("ldmatrix.sync.aligned.m8n8.x4.shared.b16 {%0,%1,%2,%3}, [%4];"
                 : "=r"(r0), "=r"(r1), "=r"(r2), "=r"(r3) : "r"(addr));
}
__device__ __forceinline__ float4 round4(float4 v) {
    float4 w;
    w.x = __uint_as_float(f2tf32(v.x));
    w.y = __uint_as_float(f2tf32(v.y));
    w.z = __uint_as_float(f2tf32(v.z));
    w.w = __uint_as_float(f2tf32(v.w));
    return w;
}
__device__ __forceinline__ uint32_t smem_u32(const void* p) {
    uint32_t a;
    asm("{ .reg .u64 t; cvta.to.shared.u64 t, %1; cvt.u32.u64 %0, t; }" : "=r"(a) : "l"(p));
    return a;
}
__device__ __forceinline__ void cpasync16(uint32_t dst, const void* src, int szbytes) {
    asm volatile("cp.async.ca.shared.global [%0], [%1], 16, %2;"
                 :: "r"(dst), "l"(src), "r"(szbytes));
}

// ---------------------------------------------------------------------------
__global__ __launch_bounds__(256) void round_buf(const float4* __restrict__ in,
                                                 float4* __restrict__ out, int n4) {
    int i = blockIdx.x * blockDim.x + threadIdx.x;
    int stride = gridDim.x * blockDim.x;
    for (; i < n4; i += stride) out[i] = round4(in[i]);
}

__global__ __launch_bounds__(256) void round_tr(const float* __restrict__ W,
                                                float* __restrict__ Wt,
                                                int Kdim, int Ncols) {
    __shared__ float tb[32][33];
    const int n0 = blockIdx.x * 32, k0 = blockIdx.y * 32;
#pragma unroll
    for (int i = threadIdx.y; i < 32; i += 8)
        tb[i][threadIdx.x] = W[(size_t)(k0 + i) * Ncols + n0 + threadIdx.x];
    __syncthreads();
#pragma unroll
    for (int i = threadIdx.y; i < 32; i += 8)
        Wt[(size_t)(n0 + i) * Kdim + k0 + threadIdx.x] =
            __uint_as_float(f2tf32(tb[threadIdx.x][i]));
}

// ---------------------------------------------------------------------------
// tf32 mma GEMM (R13-validated, unchanged).
// ---------------------------------------------------------------------------
__global__ __launch_bounds__(256, 2) void gemm_mma(const float* __restrict__ A,
                                                   const float* __restrict__ Bt,
                                                   const float* __restrict__ bias,
                                                   float* __restrict__ outp,
                                                   int Mtotal, int mode) {
    extern __shared__ float smg[];
    const uint32_t sbase = smem_u32(smg);

    const int tid = threadIdx.x;
    const int lane = tid & 31, wid = tid >> 5;
    const int warpM = wid >> 1, warpN = wid & 1;
    const int g = lane >> 2, t = lane & 3;
    const int m0 = blockIdx.y * 128, n0 = blockIdx.x * 128;

    uint32_t aoff[2];
#pragma unroll
    for (int mf = 0; mf < 2; mf++)
        aoff[mf] = ((warpM * 32 + mf * 16 + (lane & 15)) * AST + ((lane >> 4) & 1) * 4) * 4;
    uint32_t boff[4];
#pragma unroll
    for (int p = 0; p < 4; p++)
        boff[p] = (128 * AST +
                   (warpN * 64 + p * 16 + (lane >> 4) * 8 + (lane & 7)) * AST +
                   ((lane >> 3) & 1) * 4) * 4;

#define STAGE(kt, b)                                                              \
    {                                                                             \
        const int k0 = (kt) * 32;                                                 \
        const uint32_t base = sbase + (uint32_t)(b) * (GBUF * 4);                 \
        _Pragma("unroll")                                                         \
        for (int u = 0; u < 4; u++) {                                             \
            int idx = tid + u * 256;                                              \
            int r = idx >> 3, c4 = idx & 7;                                       \
            int row = m0 + r;                                                     \
            int rc = row < Mtotal ? row : Mtotal - 1;                             \
            cpasync16(base + (uint32_t)(r * AST + c4 * 4) * 4,                    \
                      A + (size_t)rc * DIM + k0 + c4 * 4,                         \
                      row < Mtotal ? 16 : 0);                                     \
        }                                                                         \
        _Pragma("unroll")                                                         \
        for (int u = 0; u < 4; u++) {                                             \
            int idx = tid + u * 256;                                              \
            int r = idx >> 3, c4 = idx & 7;                                       \
            cpasync16(base + (uint32_t)(128 * AST + r * AST + c4 * 4) * 4,        \
                      Bt + (size_t)(n0 + r) * DIM + k0 + c4 * 4, 16);             \
        }                                                                         \
    }

    float d[2][8][4];
#pragma unroll
    for (int i = 0; i < 2; i++)
#pragma unroll
        for (int j = 0; j < 8; j++)
#pragma unroll
            for (int c = 0; c < 4; c++) d[i][j][c] = 0.f;

    STAGE(0, 0);
    asm volatile("cp.async.commit_group;");
    asm volatile("cp.async.wait_group 0;");
    __syncthreads();

    for (int kt = 0; kt < 24; kt++) {
        const int cur = kt & 1;
        if (kt < 23) {
            STAGE(kt + 1, 1 - cur);
            asm volatile("cp.async.commit_group;");
        }

        const uint32_t bufb = sbase + (uint32_t)cur * (GBUF * 4);
#pragma unroll
        for (int ks = 0; ks < 4; ks++) {
            const uint32_t kboff = ks * 8 * 4;
            uint32_t af[2][4], bf[8][2];
#pragma unroll
            for (int mf = 0; mf < 2; mf++)
                ldsm4(af[mf][0], af[mf][1], af[mf][2], af[mf][3],
                      bufb + aoff[mf] + kboff);
#pragma unroll
            for (int p = 0; p < 4; p++)
                ldsm4(bf[2 * p][0], bf[2 * p][1], bf[2 * p + 1][0], bf[2 * p + 1][1],
                      bufb + boff[p] + kboff);
#pragma unroll
            for (int mf = 0; mf < 2; mf++)
#pragma unroll
                for (int nf = 0; nf < 8; nf++) mma1688(d[mf][nf], af[mf], bf[nf]);
        }
        if (kt < 23) asm volatile("cp.async.wait_group 0;");
        __syncthreads();
    }

#pragma unroll
    for (int mf = 0; mf < 2; mf++) {
#pragma unroll
        for (int half = 0; half < 2; half++) {
            int row = m0 + warpM * 32 + mf * 16 + g + half * 8;
            if (row >= Mtotal) continue;
            int b_ = row / SEQ, n = row - (row / SEQ) * SEQ;
#pragma unroll
            for (int nf = 0; nf < 8; nf++) {
                int col = n0 + warpN * 64 + nf * 8 + 2 * t;
                float2 w;
                w.x = d[mf][nf][half * 2 + 0] + bias[col + 0];
                w.y = d[mf][nf][half * 2 + 1] + bias[col + 1];
                if (mode == 0) {
                    w.x = __uint_as_float(f2tf32(w.x));
                    w.y = __uint_as_float(f2tf32(w.y));
                    int s = col / DIM;
                    int rem = col - s * DIM;
                    int h = rem >> 6, dd = rem & 63;
                    *(float2*)(g_qkv +
                        (((size_t)s * NBH + b_ * NHEADS + h) * SEQ + n) * HD + dd) = w;
                } else {
                    *(float2*)(outp + (size_t)row * DIM + col) = w;
                }
            }
        }
    }
#undef STAGE
}

// ---------------------------------------------------------------------------
__global__ __launch_bounds__(256) void vsum_kernel() {
    __shared__ float part[4][64];
    const int bh = blockIdx.x;
    const int c = threadIdx.x & 63, gr = threadIdx.x >> 6;
    const float* Vg = g_qkv + (size_t)(2 * NBH + bh) * SEQ * HD;
    float s = 0.f;
    for (int k = gr; k < SEQ; k += 4) s += Vg[(size_t)k * HD + c];
    part[gr][c] = s;
    __syncthreads();
    if (gr == 0)
        g_vsum[bh * HD + c] = part[0][c] + part[1][c] + part[2][c] + part[3][c];
}

// ---------------------------------------------------------------------------
// Tensor-core attention (R13 structure, single-buffered) with SPLIT K/V
// commit groups: wait for K before S-MMA, wait for V only after softmax.
// ---------------------------------------------------------------------------
__global__ __launch_bounds__(256, 2) void attn_mma(const float* __restrict__ policy) {
    extern __shared__ float sm[];
    float* Vs = sm + 64 * KSTK;                 // 64 x VST
    float* polAll = sm + 64 * KSTK + 64 * VST + 128 * PST;

    const uint32_t sbase = smem_u32(sm);
    const uint32_t ksBase = sbase;
    const uint32_t vsBase = sbase + 64 * KSTK * 4;
    const uint32_t psBase = vsBase + 64 * VST * 4;

    const int bh = blockIdx.y;
    const int b_ = bh / NHEADS, h = bh % NHEADS;
    const int q0 = blockIdx.x * 128;
    const float* Qg = g_qkv + (size_t)bh * SEQ * HD;
    const float* Kg = g_qkv + (size_t)(NBH + bh) * SEQ * HD;
    const float* Vg = g_qkv + (size_t)(2 * NBH + bh) * SEQ * HD;

    const int tid = threadIdx.x;
    const int lane = tid & 31, w = tid >> 5;
    const int g = lane >> 2, t = lane & 3;
    const int r0 = q0 + w * 16 + g;

    for (int i = tid; i < POLPAD; i += 256)
        polAll[i] = (i < SEQ) ? policy[b_ * SEQ + i] : 0.f;

    uint32_t koff[4];
#pragma unroll
    for (int p = 0; p < 4; p++)
        koff[p] = ((p * 16 + (lane >> 4) * 8 + (lane & 7)) * KSTK +
                   ((lane >> 3) & 1) * 4) * 4;
    const uint32_t poff = ((w * 16 + (lane & 15)) * PST + ((lane >> 4) & 1) * 4) * 4;

    // Q frags (canonical slot order)
    uint32_t aq[8][4];
#pragma unroll
    for (int ks = 0; ks < 8; ks++) {
        int c = ks * 8 + t;
        aq[ks][0] = (r0 < SEQ)     ? f2tf32(Qg[(size_t)r0 * HD + c])           : 0u;
        aq[ks][1] = (r0 + 8 < SEQ) ? f2tf32(Qg[(size_t)(r0 + 8) * HD + c])     : 0u;
        aq[ks][2] = (r0 < SEQ)     ? f2tf32(Qg[(size_t)r0 * HD + c + 4])       : 0u;
        aq[ks][3] = (r0 + 8 < SEQ) ? f2tf32(Qg[(size_t)(r0 + 8) * HD + c + 4]) : 0u;
    }

    float mrow[2] = {-1e30f, -1e30f}, lrow[2] = {0.f, 0.f};
    float o[8][4];
#pragma unroll
    for (int nf = 0; nf < 8; nf++)
#pragma unroll
        for (int c = 0; c < 4; c++) o[nf][c] = 0.f;

    for (int kc = 0; kc < 10; kc++) {
        const int kb = kc * 64;
        __syncthreads();   // all warps done reading previous Ks/Vs/Ps
        // stage K (group A)
#pragma unroll
        for (int u = 0; u < 4; u++) {
            int idx = tid + u * 256;
            int r = idx >> 4, c4 = idx & 15;
            int row = kb + r;
            int rc = row < SEQ ? row : SEQ - 1;
            cpasync16(ksBase + (uint32_t)(r * KSTK + c4 * 4) * 4,
                      Kg + (size_t)rc * HD + c4 * 4, row < SEQ ? 16 : 0);
        }
        asm volatile("cp.async.commit_group;");
        // stage V (group B) — not needed until after softmax
#pragma unroll
        for (int u = 0; u < 4; u++) {
            int idx = tid + u * 256;
            int r = idx >> 4, c4 = idx & 15;
            int row = kb + r;
            int rc = row < SEQ ? row : SEQ - 1;
            cpasync16(vsBase + (uint32_t)(r * VST + c4 * 4) * 4,
                      Vg + (size_t)rc * HD + c4 * 4, row < SEQ ? 16 : 0);
        }
        asm volatile("cp.async.commit_group;");

        asm volatile("cp.async.wait_group 1;");   // K resident (V may be in flight)
        __syncthreads();

        // S = Q K^T (K frags via ldmatrix)
        float s[8][4];
#pragma unroll
        for (int nf = 0; nf < 8; nf++)
#pragma unroll
            for (int c = 0; c < 4; c++) s[nf][c] = 0.f;
#pragma unroll
        for (int ks = 0; ks < 8; ks++) {
            const uint32_t kcoff = ks * 8 * 4;
            uint32_t bf[8][2];
#pragma unroll
            for (int p = 0; p < 4; p++)
                ldsm4(bf[2 * p][0], bf[2 * p][1], bf[2 * p + 1][0], bf[2 * p + 1][1],
                      ksBase + koff[p] + kcoff);
#pragma unroll
            for (int nf = 0; nf < 8; nf++) mma1688(s[nf], aq[ks], bf[nf]);
        }

#pragma unroll
        for (int nf = 0; nf < 8; nf++)
#pragma unroll
            for (int c = 0; c < 4; c++) {
                int key = kb + nf * 8 + 2 * t + (c & 1);
                s[nf][c] = (key < SEQ) ? s[nf][c] * ATT_SCALE : -1e30f;
            }

#pragma unroll
        for (int half = 0; half < 2; half++) {
            const int qglob = r0 + 8 * half;
            float rm = -1e30f;
#pragma unroll
            for (int nf = 0; nf < 8; nf++)
                rm = fmaxf(rm, fmaxf(s[nf][half * 2], s[nf][half * 2 + 1]));
            rm = fmaxf(rm, __shfl_xor_sync(0xffffffffu, rm, 1));
            rm = fmaxf(rm, __shfl_xor_sync(0xffffffffu, rm, 2));
            float nm = fmaxf(mrow[half], rm);
            float corr = __expf(mrow[half] - nm);
            mrow[half] = nm;
            float ls = 0.f;
#pragma unroll
            for (int nf = 0; nf < 8; nf++) {
#pragma unroll
                for (int c = 0; c < 2; c++) {
                    int kl = nf * 8 + 2 * t + c;
                    int key = kb + kl;
                    bool keep = (polAll[kb + kl] > 0.5f) || (key == qglob);
                    float p = keep ? __expf(s[nf][half * 2 + c] - nm) : 0.f;
                    s[nf][half * 2 + c] = p;
                    ls += p;
                }
            }
            ls += __shfl_xor_sync(0xffffffffu, ls, 1);
            ls += __shfl_xor_sync(0xffffffffu, ls, 2);
            lrow[half] = lrow[half] * corr + ls;
#pragma unroll
            for (int nf = 0; nf < 8; nf++) {
                o[nf][half * 2] *= corr;
                o[nf][half * 2 + 1] *= corr;
            }
        }

        // P -> smem (warp-private rows; no barrier needed)
        float* Ps = sm + 64 * KSTK + 64 * VST;
#pragma unroll
        for (int nf = 0; nf < 8; nf++) {
#pragma unroll
            for (int half = 0; half < 2; half++) {
                float2 pv;
                pv.x = __uint_as_float(f2tf32(s[nf][half * 2]));
                pv.y = __uint_as_float(f2tf32(s[nf][half * 2 + 1]));
                *(float2*)(Ps + (w * 16 + g + 8 * half) * PST + nf * 8 + 2 * t) = pv;
            }
        }

        asm volatile("cp.async.wait_group 0;");   // V resident (hidden behind softmax)
        __syncthreads();

        // O += P V  (P frag via ldmatrix; V canonical rows kcol+t, kcol+t+4)
#pragma unroll
        for (int ks = 0; ks < 8; ks++) {
            const int kcol = ks * 8;
            uint32_t ap[4];
            ldsm4(ap[0], ap[1], ap[2], ap[3], psBase + poff + (uint32_t)kcol * 4);
#pragma unroll
            for (int nf = 0; nf < 8; nf++) {
                int c0 = nf * 8 + g;
                uint32_t bf[2];
                bf[0] = __float_as_uint(Vs[(kcol + t) * VST + c0]);
                bf[1] = __float_as_uint(Vs[(kcol + t + 4) * VST + c0]);
                mma1688(o[nf], ap, bf);
            }
        }
    }

    const float epsn = EPSF / (float)SEQ;
#pragma unroll
    for (int half = 0; half < 2; half++) {
        int qglob = r0 + 8 * half;
        if (qglob >= SEQ) continue;
        float inv = 1.f / (lrow[half] + EPSF);
#pragma unroll
        for (int nf = 0; nf < 8; nf++) {
            int dd = nf * 8 + 2 * t;
            float2 vs = *(const float2*)(g_vsum + bh * HD + dd);
            float2 ww;
            ww.x = __uint_as_float(f2tf32((o[nf][half * 2] + epsn * vs.x) * inv));
            ww.y = __uint_as_float(f2tf32((o[nf][half * 2 + 1] + epsn * vs.y) * inv));
            *(float2*)(g_attn + ((size_t)b_ * SEQ + qglob) * DIM + h * HD + dd) = ww;
        }
    }
}

// ---------------------------------------------------------------------------
extern "C" void kernel_launch(void* const* d_in, const int* in_sizes, int n_in,
                              void* d_out, int out_size) {
    const float* x      = (const float*)d_in[0];
    const float* policy = (const float*)d_in[1];
    const float* Wqkv   = (const float*)d_in[2];
    const float* bqkv   = (const float*)d_in[3];
    const float* Wproj  = (const float*)d_in[4];
    const float* bproj  = (const float*)d_in[5];
    float* out = (float*)d_out;
    (void)in_sizes; (void)n_in; (void)out_size;

    void *p_attn = nullptr, *p_xr = nullptr, *p_wqT = nullptr, *p_wpT = nullptr;
    cudaGetSymbolAddress(&p_attn, g_attn);
    cudaGetSymbolAddress(&p_xr, g_xr);
    cudaGetSymbolAddress(&p_wqT, g_wqT);
    cudaGetSymbolAddress(&p_wpT, g_wpT);

    // 0) pre-round x; round+transpose weights to [n][k]
    round_buf<<<1184, 256>>>((const float4*)x, (float4*)p_xr, MROWS * DIM / 4);
    dim3 tb(32, 8);
    round_tr<<<dim3(NQKV / 32, DIM / 32), tb>>>(Wqkv, (float*)p_wqT, DIM, NQKV);
    round_tr<<<dim3(DIM / 32, DIM / 32), tb>>>(Wproj, (float*)p_wpT, DIM, DIM);

    const int gsmem = 2 * GBUF * 4;   // 73728 B
    cudaFuncSetAttribute(gemm_mma, cudaFuncAttributeMaxDynamicSharedMemorySize, gsmem);

    // 1) QKV projection, scatter (rounded) to [3,B,H,N,64]
    dim3 g1(NQKV / 128, (MROWS + 127) / 128);
    gemm_mma<<<g1, 256, gsmem>>>((const float*)p_xr, (const float*)p_wqT, bqkv,
                                 nullptr, MROWS, 0);

    // 1b) per-(b,h) V column sums
    vsum_kernel<<<NBH, 256>>>();

    // 2) tensor-core policy-masked flash attention (split K/V wait)
    const int asmem = (64 * KSTK + 64 * VST + 128 * PST + POLPAD) * 4;  // 73216 B
    cudaFuncSetAttribute(attn_mma, cudaFuncAttributeMaxDynamicSharedMemorySize, asmem);
    dim3 g2((SEQ + 127) / 128, NBH);
    attn_mma<<<g2, 256, asmem>>>(policy);

    // 3) output projection
    dim3 g3(DIM / 128, (MROWS + 127) / 128);
    gemm_mma<<<g3, 256, gsmem>>>((const float*)p_attn, (const float*)p_wpT, bproj,
                                 out, MROWS, 1);
}

// round 16
// speedup vs baseline: 1.0586x; 1.0368x over previous
#include <cuda_runtime.h>
#include <cstdint>

#define NHEADS 12
#define HD 64
#define NB 16
#define SEQ 577
#define DIM 768
#define MROWS (NB * SEQ)        // 9232
#define NQKV (3 * DIM)          // 2304
#define NBH (NB * NHEADS)       // 192
#define ATT_SCALE 0.125f
#define EPSF 1e-6f
#define AST 36                  // GEMM smem stride (floats): ldmatrix banks 4r, CF
#define KSTK 68                 // attn K stride: ldmatrix banks 4r, CF
#define VST 68                  // attn V stride: permuted LDS.32 banks 8t+g, CF
#define GBUF (128 * AST * 2)    // floats per gemm stage (9216)
#define POLPAD 640

// Scratch (no allocations allowed)
__device__ float g_qkv[(size_t)3 * NBH * SEQ * HD];   // [3,B,H,N,64] (tf32-rounded)
__device__ float g_attn[(size_t)MROWS * DIM];         // [B*N, 768]   (tf32-rounded)
__device__ float g_vsum[(size_t)NBH * HD];
__device__ float g_xr[(size_t)MROWS * DIM];           // tf32-rounded x
__device__ float g_wqT[(size_t)NQKV * DIM];           // rounded Wqkv^T [n][k]
__device__ float g_wpT[(size_t)DIM * DIM];            // rounded Wproj^T [n][k]

__device__ __forceinline__ uint32_t f2tf32(float x) {
    uint32_t r;
    asm("cvt.rna.tf32.f32 %0, %1;" : "=r"(r) : "f"(x));
    return r;
}
__device__ __forceinline__ void mma1688(float d[4], const uint32_t a[4], const uint32_t b[2]) {
    asm volatile(
        "mma.sync.aligned.m16n8k8.row.col.f32.tf32.tf32.f32 "
        "{%0,%1,%2,%3}, {%4,%5,%6,%7}, {%8,%9}, {%0,%1,%2,%3};"
        : "+f"(d[0]), "+f"(d[1]), "+f"(d[2]), "+f"(d[3])
        : "r"(a[0]), "r"(a[1]), "r"(a[2]), "r"(a[3]), "r"(b[0]), "r"(b[1]));
}
__device__ __forceinline__ void ldsm4(uint32_t& r0, uint32_t& r1, uint32_t& r2,
                                      uint32_t& r3, uint32_t addr) {
    asm volatile("ldmatrix.sync.aligned.m8n8.x4.shared.b16 {%0,%1,%2,%3}, [%4];"
                 : "=r"(r0), "=r"(r1), "=r"(r2), "=r"(r3) : "r"(addr));
}
__device__ __forceinline__ float4 round4(float4 v) {
    float4 w;
    w.x = __uint_as_float(f2tf32(v.x));
    w.y = __uint_as_float(f2tf32(v.y));
    w.z = __uint_as_float(f2tf32(v.z));
    w.w = __uint_as_float(f2tf32(v.w));
    return w;
}
__device__ __forceinline__ uint32_t smem_u32(const void* p) {
    uint32_t a;
    asm("{ .reg .u64 t; cvta.to.shared.u64 t, %1; cvt.u32.u64 %0, t; }" : "=r"(a) : "l"(p));
    return a;
}
__device__ __forceinline__ void cpasync16(uint32_t dst, const void* src, int szbytes) {
    asm volatile("cp.async.ca.shared.global [%0], [%1], 16, %2;"
                 :: "r"(dst), "l"(src), "r"(szbytes));
}

// ---------------------------------------------------------------------------
__global__ __launch_bounds__(256) void round_buf(const float4* __restrict__ in,
                                                 float4* __restrict__ out, int n4) {
    int i = blockIdx.x * blockDim.x + threadIdx.x;
    int stride = gridDim.x * blockDim.x;
    for (; i < n4; i += stride) out[i] = round4(in[i]);
}

__global__ __launch_bounds__(256) void round_tr(const float* __restrict__ W,
                                                float* __restrict__ Wt,
                                                int Kdim, int Ncols) {
    __shared__ float tb[32][33];
    const int n0 = blockIdx.x * 32, k0 = blockIdx.y * 32;
#pragma unroll
    for (int i = threadIdx.y; i < 32; i += 8)
        tb[i][threadIdx.x] = W[(size_t)(k0 + i) * Ncols + n0 + threadIdx.x];
    __syncthreads();
#pragma unroll
    for (int i = threadIdx.y; i < 32; i += 8)
        Wt[(size_t)(n0 + i) * Kdim + k0 + threadIdx.x] =
            __uint_as_float(f2tf32(tb[threadIdx.x][i]));
}

// ---------------------------------------------------------------------------
// tf32 mma GEMM (R13-validated, unchanged).
// ---------------------------------------------------------------------------
__global__ __launch_bounds__(256, 2) void gemm_mma(const float* __restrict__ A,
                                                   const float* __restrict__ Bt,
                                                   const float* __restrict__ bias,
                                                   float* __restrict__ outp,
                                                   int Mtotal, int mode) {
    extern __shared__ float smg[];
    const uint32_t sbase = smem_u32(smg);

    const int tid = threadIdx.x;
    const int lane = tid & 31, wid = tid >> 5;
    const int warpM = wid >> 1, warpN = wid & 1;
    const int g = lane >> 2, t = lane & 3;
    const int m0 = blockIdx.y * 128, n0 = blockIdx.x * 128;

    uint32_t aoff[2];
#pragma unroll
    for (int mf = 0; mf < 2; mf++)
        aoff[mf] = ((warpM * 32 + mf * 16 + (lane & 15)) * AST + ((lane >> 4) & 1) * 4) * 4;
    uint32_t boff[4];
#pragma unroll
    for (int p = 0; p < 4; p++)
        boff[p] = (128 * AST +
                   (warpN * 64 + p * 16 + (lane >> 4) * 8 + (lane & 7)) * AST +
                   ((lane >> 3) & 1) * 4) * 4;

#define STAGE(kt, b)                                                              \
    {                                                                             \
        const int k0 = (kt) * 32;                                                 \
        const uint32_t base = sbase + (uint32_t)(b) * (GBUF * 4);                 \
        _Pragma("unroll")                                                         \
        for (int u = 0; u < 4; u++) {                                             \
            int idx = tid + u * 256;                                              \
            int r = idx >> 3, c4 = idx & 7;                                       \
            int row = m0 + r;                                                     \
            int rc = row < Mtotal ? row : Mtotal - 1;                             \
            cpasync16(base + (uint32_t)(r * AST + c4 * 4) * 4,                    \
                      A + (size_t)rc * DIM + k0 + c4 * 4,                         \
                      row < Mtotal ? 16 : 0);                                     \
        }                                                                         \
        _Pragma("unroll")                                                         \
        for (int u = 0; u < 4; u++) {                                             \
            int idx = tid + u * 256;                                              \
            int r = idx >> 3, c4 = idx & 7;                                       \
            cpasync16(base + (uint32_t)(128 * AST + r * AST + c4 * 4) * 4,        \
                      Bt + (size_t)(n0 + r) * DIM + k0 + c4 * 4, 16);             \
        }                                                                         \
    }

    float d[2][8][4];
#pragma unroll
    for (int i = 0; i < 2; i++)
#pragma unroll
        for (int j = 0; j < 8; j++)
#pragma unroll
            for (int c = 0; c < 4; c++) d[i][j][c] = 0.f;

    STAGE(0, 0);
    asm volatile("cp.async.commit_group;");
    asm volatile("cp.async.wait_group 0;");
    __syncthreads();

    for (int kt = 0; kt < 24; kt++) {
        const int cur = kt & 1;
        if (kt < 23) {
            STAGE(kt + 1, 1 - cur);
            asm volatile("cp.async.commit_group;");
        }

        const uint32_t bufb = sbase + (uint32_t)cur * (GBUF * 4);
#pragma unroll
        for (int ks = 0; ks < 4; ks++) {
            const uint32_t kboff = ks * 8 * 4;
            uint32_t af[2][4], bf[8][2];
#pragma unroll
            for (int mf = 0; mf < 2; mf++)
                ldsm4(af[mf][0], af[mf][1], af[mf][2], af[mf][3],
                      bufb + aoff[mf] + kboff);
#pragma unroll
            for (int p = 0; p < 4; p++)
                ldsm4(bf[2 * p][0], bf[2 * p][1], bf[2 * p + 1][0], bf[2 * p + 1][1],
                      bufb + boff[p] + kboff);
#pragma unroll
            for (int mf = 0; mf < 2; mf++)
#pragma unroll
                for (int nf = 0; nf < 8; nf++) mma1688(d[mf][nf], af[mf], bf[nf]);
        }
        if (kt < 23) asm volatile("cp.async.wait_group 0;");
        __syncthreads();
    }

#pragma unroll
    for (int mf = 0; mf < 2; mf++) {
#pragma unroll
        for (int half = 0; half < 2; half++) {
            int row = m0 + warpM * 32 + mf * 16 + g + half * 8;
            if (row >= Mtotal) continue;
            int b_ = row / SEQ, n = row - (row / SEQ) * SEQ;
#pragma unroll
            for (int nf = 0; nf < 8; nf++) {
                int col = n0 + warpN * 64 + nf * 8 + 2 * t;
                float2 w;
                w.x = d[mf][nf][half * 2 + 0] + bias[col + 0];
                w.y = d[mf][nf][half * 2 + 1] + bias[col + 1];
                if (mode == 0) {
                    w.x = __uint_as_float(f2tf32(w.x));
                    w.y = __uint_as_float(f2tf32(w.y));
                    int s = col / DIM;
                    int rem = col - s * DIM;
                    int h = rem >> 6, dd = rem & 63;
                    *(float2*)(g_qkv +
                        (((size_t)s * NBH + b_ * NHEADS + h) * SEQ + n) * HD + dd) = w;
                } else {
                    *(float2*)(outp + (size_t)row * DIM + col) = w;
                }
            }
        }
    }
#undef STAGE
}

// ---------------------------------------------------------------------------
__global__ __launch_bounds__(256) void vsum_kernel() {
    __shared__ float part[4][64];
    const int bh = blockIdx.x;
    const int c = threadIdx.x & 63, gr = threadIdx.x >> 6;
    const float* Vg = g_qkv + (size_t)(2 * NBH + bh) * SEQ * HD;
    float s = 0.f;
    for (int k = gr; k < SEQ; k += 4) s += Vg[(size_t)k * HD + c];
    part[gr][c] = s;
    __syncthreads();
    if (gr == 0)
        g_vsum[bh * HD + c] = part[0][c] + part[1][c] + part[2][c] + part[3][c];
}

// ---------------------------------------------------------------------------
// Tensor-core attention: NO P round-trip. Under the O-MMA key-permutation
// (logical k {t,t+4} <-> physical {2t,2t+1}), the S-MMA C-fragment IS the
// O-MMA A-fragment: a = {s0, s2, s1, s3}. V read at permuted rows (R12 path).
// ---------------------------------------------------------------------------
__global__ __launch_bounds__(256, 2) void attn_mma(const float* __restrict__ policy) {
    extern __shared__ float sm[];
    float* Vs = sm + 64 * KSTK;                 // 64 x VST
    float* polAll = sm + 64 * KSTK + 64 * VST;  // POLPAD

    const uint32_t sbase = smem_u32(sm);
    const uint32_t ksBase = sbase;
    const uint32_t vsBase = sbase + 64 * KSTK * 4;

    const int bh = blockIdx.y;
    const int b_ = bh / NHEADS, h = bh % NHEADS;
    const int q0 = blockIdx.x * 128;
    const float* Qg = g_qkv + (size_t)bh * SEQ * HD;
    const float* Kg = g_qkv + (size_t)(NBH + bh) * SEQ * HD;
    const float* Vg = g_qkv + (size_t)(2 * NBH + bh) * SEQ * HD;

    const int tid = threadIdx.x;
    const int lane = tid & 31, w = tid >> 5;
    const int g = lane >> 2, t = lane & 3;
    const int r0 = q0 + w * 16 + g;

    for (int i = tid; i < POLPAD; i += 256)
        polAll[i] = (i < SEQ) ? policy[b_ * SEQ + i] : 0.f;

    uint32_t koff[4];
#pragma unroll
    for (int p = 0; p < 4; p++)
        koff[p] = ((p * 16 + (lane >> 4) * 8 + (lane & 7)) * KSTK +
                   ((lane >> 3) & 1) * 4) * 4;

    // Q frags (canonical slot order)
    uint32_t aq[8][4];
#pragma unroll
    for (int ks = 0; ks < 8; ks++) {
        int c = ks * 8 + t;
        aq[ks][0] = (r0 < SEQ)     ? f2tf32(Qg[(size_t)r0 * HD + c])           : 0u;
        aq[ks][1] = (r0 + 8 < SEQ) ? f2tf32(Qg[(size_t)(r0 + 8) * HD + c])     : 0u;
        aq[ks][2] = (r0 < SEQ)     ? f2tf32(Qg[(size_t)r0 * HD + c + 4])       : 0u;
        aq[ks][3] = (r0 + 8 < SEQ) ? f2tf32(Qg[(size_t)(r0 + 8) * HD + c + 4]) : 0u;
    }

    float mrow[2] = {-1e30f, -1e30f}, lrow[2] = {0.f, 0.f};
    float o[8][4];
#pragma unroll
    for (int nf = 0; nf < 8; nf++)
#pragma unroll
        for (int c = 0; c < 4; c++) o[nf][c] = 0.f;

    for (int kc = 0; kc < 10; kc++) {
        const int kb = kc * 64;
        __syncthreads();   // all warps done reading previous Ks/Vs
#pragma unroll
        for (int u = 0; u < 4; u++) {
            int idx = tid + u * 256;
            int r = idx >> 4, c4 = idx & 15;
            int row = kb + r;
            int rc = row < SEQ ? row : SEQ - 1;
            cpasync16(ksBase + (uint32_t)(r * KSTK + c4 * 4) * 4,
                      Kg + (size_t)rc * HD + c4 * 4, row < SEQ ? 16 : 0);
        }
#pragma unroll
        for (int u = 0; u < 4; u++) {
            int idx = tid + u * 256;
            int r = idx >> 4, c4 = idx & 15;
            int row = kb + r;
            int rc = row < SEQ ? row : SEQ - 1;
            cpasync16(vsBase + (uint32_t)(r * VST + c4 * 4) * 4,
                      Vg + (size_t)rc * HD + c4 * 4, row < SEQ ? 16 : 0);
        }
        asm volatile("cp.async.commit_group;");
        asm volatile("cp.async.wait_group 0;");
        __syncthreads();

        // S = Q K^T (K frags via ldmatrix); s[ks][c]: c0=[g][2t] c1=[g][2t+1]
        // c2=[g+8][2t] c3=[g+8][2t+1], keys kb + ks*8 + ...
        float s[8][4];
#pragma unroll
        for (int nf = 0; nf < 8; nf++)
#pragma unroll
            for (int c = 0; c < 4; c++) s[nf][c] = 0.f;
#pragma unroll
        for (int ks = 0; ks < 8; ks++) {
            const uint32_t kcoff = ks * 8 * 4;
            uint32_t bf[8][2];
#pragma unroll
            for (int p = 0; p < 4; p++)
                ldsm4(bf[2 * p][0], bf[2 * p][1], bf[2 * p + 1][0], bf[2 * p + 1][1],
                      ksBase + koff[p] + kcoff);
#pragma unroll
            for (int nf = 0; nf < 8; nf++) mma1688(s[nf], aq[ks], bf[nf]);
        }

#pragma unroll
        for (int nf = 0; nf < 8; nf++)
#pragma unroll
            for (int c = 0; c < 4; c++) {
                int key = kb + nf * 8 + 2 * t + (c & 1);
                s[nf][c] = (key < SEQ) ? s[nf][c] * ATT_SCALE : -1e30f;
            }

        // online softmax (tree-split partial sums)
#pragma unroll
        for (int half = 0; half < 2; half++) {
            const int qglob = r0 + 8 * half;
            float rm = -1e30f;
#pragma unroll
            for (int nf = 0; nf < 8; nf++)
                rm = fmaxf(rm, fmaxf(s[nf][half * 2], s[nf][half * 2 + 1]));
            rm = fmaxf(rm, __shfl_xor_sync(0xffffffffu, rm, 1));
            rm = fmaxf(rm, __shfl_xor_sync(0xffffffffu, rm, 2));
            float nm = fmaxf(mrow[half], rm);
            float corr = __expf(mrow[half] - nm);
            mrow[half] = nm;
            float lsA = 0.f, lsB = 0.f;
#pragma unroll
            for (int nf = 0; nf < 8; nf++) {
                int kl0 = nf * 8 + 2 * t;
                bool keep0 = (polAll[kb + kl0] > 0.5f) || (kb + kl0 == qglob);
                float p0 = keep0 ? __expf(s[nf][half * 2] - nm) : 0.f;
                s[nf][half * 2] = p0;
                lsA += p0;
                bool keep1 = (polAll[kb + kl0 + 1] > 0.5f) || (kb + kl0 + 1 == qglob);
                float p1 = keep1 ? __expf(s[nf][half * 2 + 1] - nm) : 0.f;
                s[nf][half * 2 + 1] = p1;
                lsB += p1;
            }
            float ls = lsA + lsB;
            ls += __shfl_xor_sync(0xffffffffu, ls, 1);
            ls += __shfl_xor_sync(0xffffffffu, ls, 2);
            lrow[half] = lrow[half] * corr + ls;
#pragma unroll
            for (int nf = 0; nf < 8; nf++) {
                o[nf][half * 2] *= corr;
                o[nf][half * 2 + 1] *= corr;
            }
        }

        // O += P V directly from registers (k-permuted O-MMA):
        // A-frag = {s0, s2, s1, s3}; B = V rows kcol+2t, kcol+2t+1 (CF banks 8t+g)
#pragma unroll
        for (int ks = 0; ks < 8; ks++) {
            const int kcol = ks * 8;
            uint32_t ap[4];
            ap[0] = f2tf32(s[ks][0]);
            ap[1] = f2tf32(s[ks][2]);
            ap[2] = f2tf32(s[ks][1]);
            ap[3] = f2tf32(s[ks][3]);
#pragma unroll
            for (int nf = 0; nf < 8; nf++) {
                int c0 = nf * 8 + g;
                uint32_t bf[2];
                bf[0] = __float_as_uint(Vs[(kcol + 2 * t) * VST + c0]);
                bf[1] = __float_as_uint(Vs[(kcol + 2 * t + 1) * VST + c0]);
                mma1688(o[nf], ap, bf);
            }
        }
    }

    const float epsn = EPSF / (float)SEQ;
#pragma unroll
    for (int half = 0; half < 2; half++) {
        int qglob = r0 + 8 * half;
        if (qglob >= SEQ) continue;
        float inv = 1.f / (lrow[half] + EPSF);
#pragma unroll
        for (int nf = 0; nf < 8; nf++) {
            int dd = nf * 8 + 2 * t;
            float2 vs = *(const float2*)(g_vsum + bh * HD + dd);
            float2 ww;
            ww.x = __uint_as_float(f2tf32((o[nf][half * 2] + epsn * vs.x) * inv));
            ww.y = __uint_as_float(f2tf32((o[nf][half * 2 + 1] + epsn * vs.y) * inv));
            *(float2*)(g_attn + ((size_t)b_ * SEQ + qglob) * DIM + h * HD + dd) = ww;
        }
    }
}

// ---------------------------------------------------------------------------
extern "C" void kernel_launch(void* const* d_in, const int* in_sizes, int n_in,
                              void* d_out, int out_size) {
    const float* x      = (const float*)d_in[0];
    const float* policy = (const float*)d_in[1];
    const float* Wqkv   = (const float*)d_in[2];
    const float* bqkv   = (const float*)d_in[3];
    const float* Wproj  = (const float*)d_in[4];
    const float* bproj  = (const float*)d_in[5];
    float* out = (float*)d_out;
    (void)in_sizes; (void)n_in; (void)out_size;

    void *p_attn = nullptr, *p_xr = nullptr, *p_wqT = nullptr, *p_wpT = nullptr;
    cudaGetSymbolAddress(&p_attn, g_attn);
    cudaGetSymbolAddress(&p_xr, g_xr);
    cudaGetSymbolAddress(&p_wqT, g_wqT);
    cudaGetSymbolAddress(&p_wpT, g_wpT);

    // 0) pre-round x; round+transpose weights to [n][k]
    round_buf<<<1184, 256>>>((const float4*)x, (float4*)p_xr, MROWS * DIM / 4);
    dim3 tb(32, 8);
    round_tr<<<dim3(NQKV / 32, DIM / 32), tb>>>(Wqkv, (float*)p_wqT, DIM, NQKV);
    round_tr<<<dim3(DIM / 32, DIM / 32), tb>>>(Wproj, (float*)p_wpT, DIM, DIM);

    const int gsmem = 2 * GBUF * 4;   // 73728 B
    cudaFuncSetAttribute(gemm_mma, cudaFuncAttributeMaxDynamicSharedMemorySize, gsmem);

    // 1) QKV projection, scatter (rounded) to [3,B,H,N,64]
    dim3 g1(NQKV / 128, (MROWS + 127) / 128);
    gemm_mma<<<g1, 256, gsmem>>>((const float*)p_xr, (const float*)p_wqT, bqkv,
                                 nullptr, MROWS, 0);

    // 1b) per-(b,h) V column sums
    vsum_kernel<<<NBH, 256>>>();

    // 2) tensor-core policy-masked flash attention (register-resident P)
    const int asmem = (64 * KSTK + 64 * VST + POLPAD) * 4;  // 37376 B
    cudaFuncSetAttribute(attn_mma, cudaFuncAttributeMaxDynamicSharedMemorySize, asmem);
    dim3 g2((SEQ + 127) / 128, NBH);
    attn_mma<<<g2, 256, asmem>>>(policy);

    // 3) output projection
    dim3 g3(DIM / 128, (MROWS + 127) / 128);
    gemm_mma<<<g3, 256, gsmem>>>((const float*)p_attn, (const float*)p_wpT, bproj,
                                 out, MROWS, 1);
}